// round 15
// baseline (speedup 1.0000x reference)
#include <cuda_runtime.h>
#include <cuda_bf16.h>

// FlyVisAdExODE: event-driven COBA scatter + AdEx Euler step.
// N = 131072 neurons, E = N*64 = 8388608 edges.
//
// R10: warp-aggregated compaction in the scatter. Previous versions paid
// 2-3 BSSY/BSYNC divergent-region penalties (~33-56cyc each) per warp-iter
// because ~every warp had a few scattered active lanes. Now: ballot the
// active 4-edge groups, lanes 0..cnt-1 process the COMPACTED groups (one
// clean predicated region; inner atomics are single-instr @P RED).
// Byte code table (128KB smem, 1 block/SM — occupancy proven non-binding
// in R9). Packed u32 counter atomics (exc low16 / inh hi16): deterministic.
// g_cnt zero-at-entry invariant: static zero-init on first call, re-armed by
// update_kernel every call => graph-replay safe.

#define NMAX 131072
#define NBLK 148
#define NTHR 1024

__device__ unsigned int  g_cnt[NMAX];   // zero-initialized at module load
__device__ unsigned char g_code[NMAX];  // byte codes: 0 idle, 1 exc, 2 inh

// ---------------------------------------------------------------------------
// Phase 1: build byte codes, 4 neurons/thread -> uchar4 store.
// spiked / is_excitatory are 4-byte (int32 or float32): nonzero-u32 test is
// correct for both encodings.
// ---------------------------------------------------------------------------
__global__ void prep_kernel(const uint4* __restrict__ spiked,
                            const uint4* __restrict__ is_exc) {
    int t = blockIdx.x * blockDim.x + threadIdx.x;   // N/4 threads
    uint4 s = spiked[t];
    uint4 e = is_exc[t];
    uchar4 c;
    c.x = s.x ? (e.x ? 1 : 2) : 0;
    c.y = s.y ? (e.y ? 1 : 2) : 0;
    c.z = s.z ? (e.z ? 1 : 2) : 0;
    c.w = s.w ? (e.w ? 1 : 2) : 0;
    reinterpret_cast<uchar4*>(g_code)[t] = c;
}

// ---------------------------------------------------------------------------
// Phase 2: scatter with warp-aggregated group compaction.
// Loop uniformity: e4, the grid stride, and every warp's base are multiples
// of 32, so all warp ballots execute with full masks.
// ---------------------------------------------------------------------------
__global__ __launch_bounds__(NTHR, 1)
void scatter_kernel(const int4* __restrict__ src4,
                    const int*  __restrict__ dst,
                    int e4) {
    extern __shared__ unsigned char tbl[];          // 131072 bytes

    // stage byte table from L2 into smem (8 uint4 per thread)
    {
        const uint4* gc = reinterpret_cast<const uint4*>(g_code);
        uint4* st = reinterpret_cast<uint4*>(tbl);
        #pragma unroll
        for (int j = 0; j < 8; j++)
            st[threadIdx.x + j * NTHR] = __ldcg(gc + threadIdx.x + j * NTHR);
    }
    __syncthreads();

    const int T = NBLK * NTHR;
    const int lane = threadIdx.x & 31;

    for (int t = blockIdx.x * NTHR + threadIdx.x; t < e4; t += T) {
        int4 s = src4[t];

        // pack this group's 4 byte codes into one u32
        unsigned pk = (unsigned)tbl[s.x]
                    | ((unsigned)tbl[s.y] << 8)
                    | ((unsigned)tbl[s.z] << 16)
                    | ((unsigned)tbl[s.w] << 24);

        unsigned mask = __ballot_sync(0xFFFFFFFFu, pk != 0u);
        int cnt = __popc(mask);
        if (cnt == 0) continue;                      // warp-uniform skip

        // lane i takes the i-th active lane's group (full-warp shfl)
        int sl = __fns(mask, 0, lane + 1);           // -1 if none
        int slc = (sl >= 0 && sl < 32) ? sl : 0;
        unsigned pko = __shfl_sync(0xFFFFFFFFu, pk, slc);

        if (lane < cnt) {
            int tt = t - lane + slc;                 // owner's group index
            int4 d = __ldg(reinterpret_cast<const int4*>(dst) + tt);
            unsigned c0 =  pko        & 0xFFu;
            unsigned c1 = (pko >> 8)  & 0xFFu;
            unsigned c2 = (pko >> 16) & 0xFFu;
            unsigned c3 =  pko >> 24;
            if (c0) atomicAdd(&g_cnt[d.x], (c0 & 1u) | ((c0 & 2u) << 15));
            if (c1) atomicAdd(&g_cnt[d.y], (c1 & 1u) | ((c1 & 2u) << 15));
            if (c2) atomicAdd(&g_cnt[d.z], (c2 & 1u) | ((c2 & 2u) << 15));
            if (c3) atomicAdd(&g_cnt[d.w], (c3 & 1u) | ((c3 & 2u) << 15));
        }
    }
}

// ---------------------------------------------------------------------------
// Phase 3: AdEx Euler update (scalar, 1 neuron/thread). Rezeroes g_cnt.
// ---------------------------------------------------------------------------
struct NeuronParams {
    const float *v, *w, *ge, *gi, *stim, *refr;
    const float *g_L, *delta_T, *v_thresh, *v_rest, *C, *a, *b;
    const float *tau_w, *tau_ge, *tau_gi;
    const float *E_ge, *E_gi, *I_bias, *stim_scale, *Q_ge, *Q_gi;
    const float *v_cut, *v_reset, *t_refrac;
    const float *dt_ptr;
    float* out;
    int n;
};

__global__ void update_kernel(NeuronParams p) {
    int i = blockIdx.x * blockDim.x + threadIdx.x;
    if (i >= p.n) return;

    const float dt = __ldg(p.dt_ptr);

    unsigned int cnt = g_cnt[i];
    g_cnt[i] = 0u;                       // re-arm for next launch
    float ge = p.ge[i] + p.Q_ge[i] * (float)(cnt & 0xFFFFu);
    float gi = p.gi[i] + p.Q_gi[i] * (float)(cnt >> 16);

    float v  = p.v[i];
    float w  = p.w[i];
    float gL = p.g_L[i];
    float dT = p.delta_T[i];
    float vr = p.v_rest[i];

    float I  = p.I_bias[i] + p.stim_scale[i] * p.stim[i]
             + ge * (p.E_ge[i] - v) + gi * (p.E_gi[i] - v);
    float ex = gL * dT * expf(fminf((v - p.v_thresh[i]) / dT, 20.0f));
    float dv = (-gL * (v - vr) + ex - w + I) / p.C[i];
    float dw = (-w + p.a[i] * (v - vr)) / p.tau_w[i];

    float refr = p.refr[i];
    float vn = (refr <= 0.0f) ? (v + dv * dt) : v;
    float wn = w + dw * dt;
    ge = ge - (ge / p.tau_ge[i]) * dt;
    gi = gi - (gi / p.tau_gi[i]) * dt;

    bool spk = vn > p.v_cut[i];
    vn = spk ? p.v_reset[i] : vn;
    wn = spk ? (wn + p.b[i]) : wn;
    float rf = (spk ? p.t_refrac[i] : refr) - dt;

    const int n = p.n;
    float* out = p.out;
    out[i]         = vn;
    out[n + i]     = wn;
    out[2 * n + i] = ge;
    out[3 * n + i] = gi;
    out[4 * n + i] = rf;
    out[5 * n + i] = spk ? 1.0f : 0.0f;
}

extern "C" void kernel_launch(void* const* d_in, const int* in_sizes, int n_in,
                              void* d_out, int out_size) {
    const int n = in_sizes[0];          // 131072
    const int E = in_sizes[27] / 2;     // 8388608

    const int* edge = (const int*)d_in[27];
    const int4* src4 = (const int4*)edge;
    const int* dst = edge + E;

    static bool attr_done = false;
    if (!attr_done) {
        cudaFuncSetAttribute(scatter_kernel,
                             cudaFuncAttributeMaxDynamicSharedMemorySize,
                             NMAX);
        attr_done = true;
    }

    // Phase 1: byte code build, 4 neurons/thread
    prep_kernel<<<n / 4 / 256, 256>>>((const uint4*)d_in[25],
                                      (const uint4*)d_in[26]);

    // Phase 2: scatter, 148 blocks x 1024 threads, 128KB smem
    scatter_kernel<<<NBLK, NTHR, NMAX>>>(src4, dst, E / 4);

    // Phase 3: neuron update (also rezeroes g_cnt)
    update_kernel<<<(n + 255) / 256, 256>>>(
        NeuronParams{
            (const float*)d_in[0],  (const float*)d_in[1],
            (const float*)d_in[2],  (const float*)d_in[3],
            (const float*)d_in[4],  (const float*)d_in[5],
            (const float*)d_in[6],  (const float*)d_in[7],
            (const float*)d_in[8],  (const float*)d_in[9],
            (const float*)d_in[10], (const float*)d_in[11],
            (const float*)d_in[12], (const float*)d_in[13],
            (const float*)d_in[14], (const float*)d_in[15],
            (const float*)d_in[16], (const float*)d_in[17],
            (const float*)d_in[18], (const float*)d_in[19],
            (const float*)d_in[20], (const float*)d_in[21],
            (const float*)d_in[22], (const float*)d_in[23],
            (const float*)d_in[24], (const float*)d_in[28],
            (float*)d_out, n});
}

// round 16
// speedup vs baseline: 1.2092x; 1.2092x over previous
#include <cuda_runtime.h>
#include <cuda_bf16.h>

// FlyVisAdExODE: event-driven COBA scatter + AdEx Euler step.
// N = 131072 neurons, E = N*64 = 8388608 edges.
//
// R11: straight-line scatter — NO branches at all in the edge loop.
// R6's loop had 3 divergent group-level BSSY/BSYNC regions per warp-iter
// (entered ~99% of the time at warp level); R10 proved removing them via
// compaction costs more than it saves, so remove them with ZERO added ops:
// always load dst4, per-edge single-instruction predicated RED (the
// `if (c) atomicAdd` single-statement arm compiles to @P RED, no BSSY).
// Byte code table (128KB smem). Packed u32 counter atomics
// (exc low16 / inh hi16): deterministic. g_cnt zero-at-entry invariant:
// static zero-init on first call, re-armed by update_kernel every call.

#define NMAX 131072
#define NBLK 148
#define NTHR 1024

__device__ unsigned int  g_cnt[NMAX];   // zero-initialized at module load
__device__ unsigned char g_code[NMAX];  // byte codes: 0 idle, 1 exc, 2 inh

// ---------------------------------------------------------------------------
// Phase 1: build byte codes, 4 neurons/thread -> uchar4 store.
// spiked / is_excitatory are 4-byte (int32 or float32): nonzero-u32 test is
// correct for both encodings.
// ---------------------------------------------------------------------------
__global__ void prep_kernel(const uint4* __restrict__ spiked,
                            const uint4* __restrict__ is_exc) {
    int t = blockIdx.x * blockDim.x + threadIdx.x;   // N/4 threads
    uint4 s = spiked[t];
    uint4 e = is_exc[t];
    uchar4 c;
    c.x = s.x ? (e.x ? 1 : 2) : 0;
    c.y = s.y ? (e.y ? 1 : 2) : 0;
    c.z = s.z ? (e.z ? 1 : 2) : 0;
    c.w = s.w ? (e.w ? 1 : 2) : 0;
    reinterpret_cast<uchar4*>(g_code)[t] = c;
}

// ---------------------------------------------------------------------------
// Phase 2: branch-free scatter. 128KB byte table in smem; per 4-edge group:
// src4 + dst4 loads, 4 LDS gathers, 4 predicated REDs. No divergent regions.
// ---------------------------------------------------------------------------
__global__ __launch_bounds__(NTHR, 1)
void scatter_kernel(const int4* __restrict__ src4,
                    const int4* __restrict__ dst4,
                    int e4) {
    extern __shared__ unsigned char tbl[];          // 131072 bytes

    // stage byte table from L2 into smem (8 uint4 per thread)
    {
        const uint4* gc = reinterpret_cast<const uint4*>(g_code);
        uint4* st = reinterpret_cast<uint4*>(tbl);
        #pragma unroll
        for (int j = 0; j < 8; j++)
            st[threadIdx.x + j * NTHR] = __ldcg(gc + threadIdx.x + j * NTHR);
    }
    __syncthreads();

    const int T = NBLK * NTHR;
    for (int t = blockIdx.x * NTHR + threadIdx.x; t < e4; t += T) {
        int4 s = src4[t];
        int4 d = __ldg(dst4 + t);

        unsigned c0 = tbl[s.x];
        unsigned c1 = tbl[s.y];
        unsigned c2 = tbl[s.z];
        unsigned c3 = tbl[s.w];

        // single-statement arms -> @P RED, no BSSY
        if (c0) atomicAdd(&g_cnt[d.x], (c0 & 1u) | ((c0 & 2u) << 15));
        if (c1) atomicAdd(&g_cnt[d.y], (c1 & 1u) | ((c1 & 2u) << 15));
        if (c2) atomicAdd(&g_cnt[d.z], (c2 & 1u) | ((c2 & 2u) << 15));
        if (c3) atomicAdd(&g_cnt[d.w], (c3 & 1u) | ((c3 & 2u) << 15));
    }
}

// ---------------------------------------------------------------------------
// Phase 3: AdEx Euler update (scalar, 1 neuron/thread). Rezeroes g_cnt.
// Fast divisions: rel_err headroom is ~4 orders of magnitude.
// ---------------------------------------------------------------------------
struct NeuronParams {
    const float *v, *w, *ge, *gi, *stim, *refr;
    const float *g_L, *delta_T, *v_thresh, *v_rest, *C, *a, *b;
    const float *tau_w, *tau_ge, *tau_gi;
    const float *E_ge, *E_gi, *I_bias, *stim_scale, *Q_ge, *Q_gi;
    const float *v_cut, *v_reset, *t_refrac;
    const float *dt_ptr;
    float* out;
    int n;
};

__global__ void update_kernel(NeuronParams p) {
    int i = blockIdx.x * blockDim.x + threadIdx.x;
    if (i >= p.n) return;

    const float dt = __ldg(p.dt_ptr);

    unsigned int cnt = g_cnt[i];
    g_cnt[i] = 0u;                       // re-arm for next launch
    float ge = p.ge[i] + p.Q_ge[i] * (float)(cnt & 0xFFFFu);
    float gi = p.gi[i] + p.Q_gi[i] * (float)(cnt >> 16);

    float v  = p.v[i];
    float w  = p.w[i];
    float gL = p.g_L[i];
    float dT = p.delta_T[i];
    float vr = p.v_rest[i];

    float I  = p.I_bias[i] + p.stim_scale[i] * p.stim[i]
             + ge * (p.E_ge[i] - v) + gi * (p.E_gi[i] - v);
    float ex = gL * dT * __expf(fminf((v - p.v_thresh[i]) * __fdividef(1.0f, dT), 20.0f));
    float dv = (-gL * (v - vr) + ex - w + I) * __fdividef(1.0f, p.C[i]);
    float dw = (-w + p.a[i] * (v - vr)) * __fdividef(1.0f, p.tau_w[i]);

    float refr = p.refr[i];
    float vn = (refr <= 0.0f) ? (v + dv * dt) : v;
    float wn = w + dw * dt;
    ge = ge - ge * __fdividef(dt, p.tau_ge[i]);
    gi = gi - gi * __fdividef(dt, p.tau_gi[i]);

    bool spk = vn > p.v_cut[i];
    vn = spk ? p.v_reset[i] : vn;
    wn = spk ? (wn + p.b[i]) : wn;
    float rf = (spk ? p.t_refrac[i] : refr) - dt;

    const int n = p.n;
    float* out = p.out;
    out[i]         = vn;
    out[n + i]     = wn;
    out[2 * n + i] = ge;
    out[3 * n + i] = gi;
    out[4 * n + i] = rf;
    out[5 * n + i] = spk ? 1.0f : 0.0f;
}

extern "C" void kernel_launch(void* const* d_in, const int* in_sizes, int n_in,
                              void* d_out, int out_size) {
    const int n = in_sizes[0];          // 131072
    const int E = in_sizes[27] / 2;     // 8388608

    const int* edge = (const int*)d_in[27];
    const int4* src4 = (const int4*)edge;
    const int4* dst4 = (const int4*)(edge + E);

    static bool attr_done = false;
    if (!attr_done) {
        cudaFuncSetAttribute(scatter_kernel,
                             cudaFuncAttributeMaxDynamicSharedMemorySize,
                             NMAX);
        attr_done = true;
    }

    // Phase 1: byte code build, 4 neurons/thread
    prep_kernel<<<n / 4 / 256, 256>>>((const uint4*)d_in[25],
                                      (const uint4*)d_in[26]);

    // Phase 2: branch-free scatter, 148 blocks x 1024 threads, 128KB smem
    scatter_kernel<<<NBLK, NTHR, NMAX>>>(src4, dst4, E / 4);

    // Phase 3: neuron update (also rezeroes g_cnt)
    update_kernel<<<(n + 255) / 256, 256>>>(
        NeuronParams{
            (const float*)d_in[0],  (const float*)d_in[1],
            (const float*)d_in[2],  (const float*)d_in[3],
            (const float*)d_in[4],  (const float*)d_in[5],
            (const float*)d_in[6],  (const float*)d_in[7],
            (const float*)d_in[8],  (const float*)d_in[9],
            (const float*)d_in[10], (const float*)d_in[11],
            (const float*)d_in[12], (const float*)d_in[13],
            (const float*)d_in[14], (const float*)d_in[15],
            (const float*)d_in[16], (const float*)d_in[17],
            (const float*)d_in[18], (const float*)d_in[19],
            (const float*)d_in[20], (const float*)d_in[21],
            (const float*)d_in[22], (const float*)d_in[23],
            (const float*)d_in[24], (const float*)d_in[28],
            (float*)d_out, n});
}